// round 17
// baseline (speedup 1.0000x reference)
#include <cuda_runtime.h>
#include <cuda_fp16.h>
#include <cstdint>
#include <math_constants.h>

// ---------------------------------------------------------------------------
// Paged-cache block-diagonal causal attention (fill chunk), fused flash-attn.
// FP16 mma.sync m16n8k16 (fp32 accum), fp32 I/O.
// R17: R16 + depth-2 cp.async pipeline (double-buffered fp32 staging,
// wait_group 1) with the convert split in two halves floated into the
// compute phase: K-convert after QK/syncA (overlaps softmax+PV), V-convert
// after PV/syncB (overlaps next QK). Tiles stay single-buffered at constant
// addresses. ctx smem prefetch, BM=128, direct sacc->PV A-frag packing,
// deferred l-reduction, tree max.
//
// kv j < 1792 -> cache[ctx32[s*2048+j]];  j >= 1792 -> new k/v row j-1792.
// Mask: kv j visible to query i iff j <= i + 1792.
// ---------------------------------------------------------------------------

namespace {
constexpr int kNSeqs   = 8;
constexpr int kQLen    = 256;
constexpr int kKvLen   = 2048;
constexpr int kHeads   = 16;
constexpr int kHeadDim = 128;
constexpr int kCtxOld  = 1792;
constexpr int kOutCols = 2048;

constexpr int BM = 128;
constexpr int BN = 64;
constexpr int kThreads = 256;  // 8 warps, 16 query rows each

constexpr float kScaleLog2e = 0.08838834764831845f * 1.4426950408889634f;

// u32 offsets. fp16 K/V tiles: 64 rows x 64 u32, XOR-swizzled
// (16B chunk index ^ (row & 7)), single-buffered (constant addresses).
// ctx slots: 1792 ints. fp32 staging: DOUBLE buffered; buffer b at
// kS0 + b*16384 (K half +0, V half +8192), 64 rows x 128 u32 per tensor.
// Q prologue (128 rows x 64 u32) aliases the K+V tile regions exactly.
constexpr int kKOff   = 0;
constexpr int kVOff   = 4096;
constexpr int kCtxOff = 8192;
constexpr int kS0     = kCtxOff + kCtxOld;        // 9984
constexpr int kStagePer = 16384;                  // one staging buffer (u32)
constexpr int kSmemU32  = kS0 + 2 * kStagePer;    // 42752 u32 = 171008 B
}  // namespace

__device__ __forceinline__ uint32_t smem_u32(const void* p) {
    uint32_t a;
    asm("{ .reg .u64 t; cvta.to.shared.u64 t, %1; cvt.u32.u64 %0, t; }"
        : "=r"(a) : "l"(p));
    return a;
}

__device__ __forceinline__ uint32_t pack2(float lo, float hi) {
    __half2 h = __floats2half2_rn(lo, hi);
    return *reinterpret_cast<uint32_t*>(&h);
}

__device__ __forceinline__ float fast_exp2(float x) {
    float r;
    asm("ex2.approx.ftz.f32 %0, %1;" : "=f"(r) : "f"(x));
    return r;
}

__device__ __forceinline__ void mma_f16(float c[4], const uint32_t a[4],
                                        const uint32_t* b) {
    asm volatile(
        "mma.sync.aligned.m16n8k16.row.col.f32.f16.f16.f32 "
        "{%0,%1,%2,%3}, {%4,%5,%6,%7}, {%8,%9}, {%0,%1,%2,%3};"
        : "+f"(c[0]), "+f"(c[1]), "+f"(c[2]), "+f"(c[3])
        : "r"(a[0]), "r"(a[1]), "r"(a[2]), "r"(a[3]), "r"(b[0]), "r"(b[1]));
}

__device__ __forceinline__ void ldm_x4(uint32_t r[4], uint32_t addr) {
    asm volatile(
        "ldmatrix.sync.aligned.m8n8.x4.shared.b16 {%0,%1,%2,%3}, [%4];"
        : "=r"(r[0]), "=r"(r[1]), "=r"(r[2]), "=r"(r[3]) : "r"(addr));
}

__device__ __forceinline__ void ldm_x4_t(uint32_t r[4], uint32_t addr) {
    asm volatile(
        "ldmatrix.sync.aligned.m8n8.x4.trans.shared.b16 {%0,%1,%2,%3}, [%4];"
        : "=r"(r[0]), "=r"(r[1]), "=r"(r[2]), "=r"(r[3]) : "r"(addr));
}

#define CP_ASYNC16(dst, src) \
    asm volatile("cp.async.cg.shared.global [%0], [%1], 16;" \
                 :: "r"(dst), "l"(src) : "memory")
#define CP_COMMIT() asm volatile("cp.async.commit_group;" ::: "memory")
#define CP_WAIT0()  asm volatile("cp.async.wait_group 0;" ::: "memory")
#define CP_WAIT1()  asm volatile("cp.async.wait_group 1;" ::: "memory")

__global__ void __launch_bounds__(kThreads, 1)
fa_fp16_kernel(const float* __restrict__ q, const float* __restrict__ kk,
               const float* __restrict__ vv, const float* __restrict__ k_cache,
               const float* __restrict__ v_cache,
               const int* __restrict__ ctx32, float* __restrict__ out) {
    extern __shared__ uint32_t smem[];
    const uint32_t sb = smem_u32(smem);

    const int qt = blockIdx.x;   // 0..1
    const int h  = blockIdx.y;   // 0..15
    const int s  = blockIdx.z;   // 0..7
    const int q0 = qt * BM;

    const int tid  = threadIdx.x;
    const int warp = tid >> 5;
    const int lane = tid & 31;
    const int g = lane >> 2;
    const int t = lane & 3;

    // ctx dtype probe (int64 LE -> odd words 1,3,5 all zero)
    const bool ctx_is64 =
        (ctx32[1] == 0) && (ctx32[3] == 0) && (ctx32[5] == 0);

    const int n_tiles = (q0 + BM - 1 + kCtxOld + 1 + BN - 1) / BN;  // 30 or 32

    const int rseg = lane >> 3;  // gather: row within group of 4
    const int c    = lane & 7;   // gather: 16B fp32 chunk within 128B pass

    // ---- issue cp.async gather of tile T into staging[T&1] ----
    auto issue_gather = [&](int T) {
        const int j0 = T * BN;
        const int sbase = kS0 + (T & 1) * kStagePer;
#pragma unroll
        for (int rg = 0; rg < 2; rg++) {
            const int row = warp * 8 + rg * 4 + rseg;
            const int j = j0 + row;
            const float *ksrc, *vsrc;
            if (j < kCtxOld) {
                const int slot = (int)smem[kCtxOff + j];
                const size_t base = ((size_t)slot * kHeads + h) * kHeadDim;
                ksrc = k_cache + base;
                vsrc = v_cache + base;
            } else {
                const size_t base =
                    ((size_t)(s * kQLen + (j - kCtxOld)) * kHeads + h) * kHeadDim;
                ksrc = kk + base;
                vsrc = vv + base;
            }
#pragma unroll
            for (int pass = 0; pass < 4; pass++) {
                const uint32_t off =
                    (uint32_t)(sbase + row * 128 + pass * 32 + c * 4) * 4;
                CP_ASYNC16(sb + off, ksrc + pass * 32 + c * 4);
                CP_ASYNC16(sb + off + (uint32_t)8192 * 4,
                           vsrc + pass * 32 + c * 4);
            }
        }
        CP_COMMIT();
    };

    // ---- convert one tensor half of staging[T&1] -> its fp16 tile ----
    auto convert_K = [&](int T) {
        const int sbase = kS0 + (T & 1) * kStagePer;
#pragma unroll
        for (int it = 0; it < 8; it++) {
            const int chunk = tid + it * 256;   // 2048 chunks
            const int row = chunk >> 5;
            const int cc  = chunk & 31;
            const int col = (((cc >> 1) ^ (row & 7)) << 2) + (cc & 1) * 2;
            float4 kf = *(const float4*)(smem + sbase + chunk * 4);
            uint2 ku;
            ku.x = pack2(kf.x, kf.y);
            ku.y = pack2(kf.z, kf.w);
            *(uint2*)(smem + kKOff + row * 64 + col) = ku;
        }
    };
    auto convert_V = [&](int T) {
        const int sbase = kS0 + (T & 1) * kStagePer + 8192;
#pragma unroll
        for (int it = 0; it < 8; it++) {
            const int chunk = tid + it * 256;
            const int row = chunk >> 5;
            const int cc  = chunk & 31;
            const int col = (((cc >> 1) ^ (row & 7)) << 2) + (cc & 1) * 2;
            float4 vf = *(const float4*)(smem + sbase + chunk * 4);
            uint2 vu;
            vu.x = pack2(vf.x, vf.y);
            vu.y = pack2(vf.z, vf.w);
            *(uint2*)(smem + kVOff + row * 64 + col) = vu;
        }
    };

    // ---- prologue A: ctx slots -> smem; Q -> smem (K+V tile region) ----
    for (int i = tid; i < kCtxOld; i += kThreads) {
        const size_t ci = (size_t)s * kKvLen + i;
        smem[kCtxOff + i] =
            (uint32_t)(ctx_is64 ? ctx32[2 * ci] : ctx32[ci]);
    }
    {
        const int r = tid >> 1;   // 0..127
        const int hh = tid & 1;
        const float* src =
            q + ((size_t)(s * kQLen + q0 + r) * kHeads + h) * kHeadDim + hh * 64;
        uint32_t* dst = smem + kKOff + r * 64 + hh * 32;  // K+V region (8192)
#pragma unroll
        for (int i = 0; i < 16; i++) {
            float4 f = *(const float4*)(src + i * 4);
            uint2 u;
            u.x = pack2(f.x * kScaleLog2e, f.y * kScaleLog2e);
            u.y = pack2(f.z * kScaleLog2e, f.w * kScaleLog2e);
            *(uint2*)(dst + 2 * i) = u;
        }
    }
    __syncthreads();  // ctx visible (gather reads it); Q visible

    // ---- prologue B: start g(0), g(1); Q frags; convert tile 0 ----
    issue_gather(0);
    issue_gather(1);

    const int qr0 = warp * 16;
    uint32_t qf[8][4];
#pragma unroll
    for (int ks = 0; ks < 8; ks++) {
        const uint32_t* r0 = smem + kKOff + (qr0 + g) * 64 + ks * 8;
        qf[ks][0] = r0[t];
        qf[ks][1] = r0[8 * 64 + t];
        qf[ks][2] = r0[t + 4];
        qf[ks][3] = r0[8 * 64 + t + 4];
    }
    CP_WAIT1();       // g(0) complete (g(1) may still fly)
    __syncthreads();  // all qf reads done before converts overwrite tiles
    convert_K(0);
    convert_V(0);
    __syncthreads();  // tile 0 visible

    float oacc[16][4];
#pragma unroll
    for (int nb = 0; nb < 16; nb++)
        oacc[nb][0] = oacc[nb][1] = oacc[nb][2] = oacc[nb][3] = 0.f;
    float m1 = -CUDART_INF_F, m2 = -CUDART_INF_F;
    float l1 = 0.f, l2 = 0.f;   // lane-partial; reduced in epilogue

    const int m_id = lane >> 3;   // ldmatrix matrix index within x4
    const int lr   = lane & 7;    // row within matrix

    for (int tile = 0; tile < n_tiles; tile++) {
        const int j0 = tile * BN;

        // ---- S = Q K^T  (b-frags via ldmatrix.x4, 2 nb per instr) ----
        float sacc[8][4];
#pragma unroll
        for (int nb = 0; nb < 8; nb++)
            sacc[nb][0] = sacc[nb][1] = sacc[nb][2] = sacc[nb][3] = 0.f;

#pragma unroll
        for (int ks = 0; ks < 8; ks++) {
#pragma unroll
            for (int nbp = 0; nbp < 4; nbp++) {
                const int row_n = nbp * 16 + (m_id >> 1) * 8 + lr;
                const uint32_t addr =
                    sb + (uint32_t)(kKOff + row_n * 64 +
                                    (((ks * 2 + (m_id & 1)) ^ (row_n & 7)) << 2)) * 4;
                uint32_t b4[4];
                ldm_x4(b4, addr);
                mma_f16(sacc[2 * nbp], qf[ks], b4);
                mma_f16(sacc[2 * nbp + 1], qf[ks], b4 + 2);
            }
        }
        __syncthreads();  // (A) all warps done reading K tile

        // staging[tile&1] fully drained (K(t+1) uses [t+1&1]; this buffer's
        // converts finished before this barrier) -> reuse for g(tile+2)
        if (tile + 2 < n_tiles) issue_gather(tile + 2);

        // retire g(tile+1), then float K(t+1) convert into the compute phase
        if (tile + 1 < n_tiles) {
            if (tile + 2 < n_tiles) { CP_WAIT1(); } else { CP_WAIT0(); }
            convert_K(tile + 1);
        }

        // ---- bottom-right causal mask (boundary tiles only) ----
        if (j0 + BN - 1 > q0 + kCtxOld) {
            const int lim1 = q0 + qr0 + g + kCtxOld;
            const int lim2 = lim1 + 8;
#pragma unroll
            for (int nb = 0; nb < 8; nb++) {
                const int c0 = j0 + nb * 8 + 2 * t;
                const int c1 = c0 + 1;
                if (c0 > lim1) sacc[nb][0] = -1e30f;
                if (c1 > lim1) sacc[nb][1] = -1e30f;
                if (c0 > lim2) sacc[nb][2] = -1e30f;
                if (c1 > lim2) sacc[nb][3] = -1e30f;
            }
        }

        // ---- online softmax (exp2 domain); tree max; P -> A-frags ----
        float t1[4], t2[4];
#pragma unroll
        for (int i = 0; i < 4; i++) {
            t1[i] = fmaxf(fmaxf(sacc[2 * i][0], sacc[2 * i][1]),
                          fmaxf(sacc[2 * i + 1][0], sacc[2 * i + 1][1]));
            t2[i] = fmaxf(fmaxf(sacc[2 * i][2], sacc[2 * i][3]),
                          fmaxf(sacc[2 * i + 1][2], sacc[2 * i + 1][3]));
        }
        float mx1 = fmaxf(fmaxf(t1[0], t1[1]), fmaxf(t1[2], t1[3]));
        float mx2 = fmaxf(fmaxf(t2[0], t2[1]), fmaxf(t2[2], t2[3]));
        mx1 = fmaxf(mx1, __shfl_xor_sync(0xffffffffu, mx1, 1));
        mx1 = fmaxf(mx1, __shfl_xor_sync(0xffffffffu, mx1, 2));
        mx2 = fmaxf(mx2, __shfl_xor_sync(0xffffffffu, mx2, 1));
        mx2 = fmaxf(mx2, __shfl_xor_sync(0xffffffffu, mx2, 2));

        const float m1n = fmaxf(m1, mx1);
        const float m2n = fmaxf(m2, mx2);
        const float al1 = fast_exp2(m1 - m1n);
        const float al2 = fast_exp2(m2 - m2n);
        m1 = m1n;
        m2 = m2n;

        // pa[nb] = fp16x2 P(rows g),  pb[nb] = fp16x2 P(rows g+8).
        // PV kstep ks: a = {pa[2ks], pb[2ks], pa[2ks+1], pb[2ks+1]}.
        uint32_t pa[8], pb[8];
        float sum1 = 0.f, sum2 = 0.f;
#pragma unroll
        for (int nb = 0; nb < 8; nb++) {
            const float p0 = fast_exp2(sacc[nb][0] - m1);
            const float p1 = fast_exp2(sacc[nb][1] - m1);
            const float p2 = fast_exp2(sacc[nb][2] - m2);
            const float p3 = fast_exp2(sacc[nb][3] - m2);
            sum1 += p0 + p1;
            sum2 += p2 + p3;
            pa[nb] = pack2(p0, p1);
            pb[nb] = pack2(p2, p3);
        }
        l1 = l1 * al1 + sum1;   // lane-partial (reduced in epilogue)
        l2 = l2 * al2 + sum2;

#pragma unroll
        for (int nb = 0; nb < 16; nb++) {
            oacc[nb][0] *= al1;
            oacc[nb][1] *= al1;
            oacc[nb][2] *= al2;
            oacc[nb][3] *= al2;
        }

        // ---- O += P V  (a from registers, b via ldmatrix.trans) ----
#pragma unroll
        for (int ks = 0; ks < 4; ks++) {
            const uint32_t a[4] = {pa[2 * ks], pb[2 * ks],
                                   pa[2 * ks + 1], pb[2 * ks + 1]};
#pragma unroll
            for (int nbp = 0; nbp < 8; nbp++) {
                const int row_j = ks * 16 + (m_id & 1) * 8 + lr;
                const uint32_t addr =
                    sb + (uint32_t)(kVOff + row_j * 64 +
                                    (((nbp * 2 + (m_id >> 1)) ^ (row_j & 7)) << 2)) * 4;
                uint32_t b4[4];
                ldm_x4_t(b4, addr);
                mma_f16(oacc[2 * nbp], a, b4);
                mma_f16(oacc[2 * nbp + 1], a, b4 + 2);
            }
        }
        __syncthreads();  // (B) V tile free; K(t+1) converts visible

        // float V(t+1) convert into the loop boundary (overlaps next QK issue)
        if (tile + 1 < n_tiles) convert_V(tile + 1);
        // next syncA orders these V writes before PV(t+1) reads them
    }

    // ---- epilogue: reduce lane-partial l, normalize, store ----
    l1 += __shfl_xor_sync(0xffffffffu, l1, 1);
    l1 += __shfl_xor_sync(0xffffffffu, l1, 2);
    l2 += __shfl_xor_sync(0xffffffffu, l2, 1);
    l2 += __shfl_xor_sync(0xffffffffu, l2, 2);
    const float inv1 = 1.f / l1;
    const float inv2 = 1.f / l2;
    const int row1 = s * kQLen + q0 + qr0 + g;
    float* o1 = out + (size_t)row1 * kOutCols + h * kHeadDim;
    float* o2 = o1 + (size_t)8 * kOutCols;
#pragma unroll
    for (int nb = 0; nb < 16; nb++) {
        const int cc = nb * 8 + 2 * t;
        float2 w1 = make_float2(oacc[nb][0] * inv1, oacc[nb][1] * inv1);
        float2 w2 = make_float2(oacc[nb][2] * inv2, oacc[nb][3] * inv2);
        *(float2*)(o1 + cc) = w1;
        *(float2*)(o2 + cc) = w2;
    }
}

extern "C" void kernel_launch(void* const* d_in, const int* in_sizes, int n_in,
                              void* d_out, int out_size) {
    const float* q  = (const float*)d_in[0];
    const float* k  = (const float*)d_in[1];
    const float* v  = (const float*)d_in[2];
    const float* kc = (const float*)d_in[3];
    const float* vc = (const float*)d_in[4];
    const int* ctx = (const int*)d_in[6];
    float* out = (float*)d_out;

    const int smem_bytes = kSmemU32 * (int)sizeof(uint32_t);
    cudaFuncSetAttribute(fa_fp16_kernel,
                         cudaFuncAttributeMaxDynamicSharedMemorySize, smem_bytes);
    dim3 grid(kQLen / BM, kHeads, kNSeqs);
    fa_fp16_kernel<<<grid, kThreads, smem_bytes>>>(q, k, v, kc, vc, ctx, out);
}